// round 14
// baseline (speedup 1.0000x reference)
#include <cuda_runtime.h>
#include <cuda_bf16.h>
#include <cuda_fp16.h>
#include <stdint.h>

#define N_NODES 4096
#define F_IN    512
#define NHEADS  4
#define DHEAD   64
#define BPAD    72

// ---------------- device scratch ----------------
__device__ float    g_ssrc[NHEADS * N_NODES];
__device__ float    g_sdst[NHEADS * N_NODES];
__device__ unsigned g_enc[2 * NHEADS];
__device__ __half   g_WxT[NHEADS * DHEAD * N_NODES];      // fp16 [h][d][n]
__device__ __nv_bfloat16 g_xhi[N_NODES * F_IN];
__device__ __nv_bfloat16 g_xlo[N_NODES * F_IN];
__device__ __nv_bfloat16 g_WT_hi[NHEADS * DHEAD * F_IN];
__device__ __nv_bfloat16 g_WT_lo[NHEADS * DHEAD * F_IN];
__device__ uint2    g_Epk[NHEADS * (N_NODES / 2)];  // per j-pair {E1E1', E2E2'} fp16x2
__device__ uint2    g_Ppk[NHEADS * N_NODES];        // per row {P1P1, P2P2} fp16x2
__device__ uint32_t g_bits[N_NODES * 128];          // adj bitmask, 2MB

// ---------------- helpers ----------------
__device__ __forceinline__ uint32_t pack_bf16x2(float lo, float hi) {
    uint32_t r;
    asm("cvt.rn.bf16x2.f32 %0, %1, %2;" : "=r"(r) : "f"(hi), "f"(lo));
    return r;
}
__device__ __forceinline__ float bf_lo_f(uint32_t w) { return __uint_as_float(w << 16); }
__device__ __forceinline__ float bf_hi_f(uint32_t w) { return __uint_as_float(w & 0xFFFF0000u); }

__device__ __forceinline__ uint32_t pack_f16x2(float lo, float hi) {
    uint32_t r;
    asm("cvt.rn.f16x2.f32 %0, %1, %2;" : "=r"(r) : "f"(hi), "f"(lo));
    return r;
}
__device__ __forceinline__ uint32_t hmul2(uint32_t a, uint32_t b) {
    uint32_t d;
    asm("mul.f16x2 %0, %1, %2;" : "=r"(d) : "r"(a), "r"(b));
    return d;
}
__device__ __forceinline__ uint32_t hmax2(uint32_t a, uint32_t b) {
    uint32_t d;
    asm("max.f16x2 %0, %1, %2;" : "=r"(d) : "r"(a), "r"(b));
    return d;
}

__device__ __forceinline__ unsigned fenc(float f) {
    unsigned u = __float_as_uint(f);
    return (u & 0x80000000u) ? ~u : (u | 0x80000000u);
}
__device__ __forceinline__ float fdec(unsigned u) {
    unsigned b = (u & 0x80000000u) ? (u & 0x7FFFFFFFu) : ~u;
    return __uint_as_float(b);
}

__device__ __forceinline__ uint32_t smem_u32(const void* p) {
    uint32_t a;
    asm("{ .reg .u64 t; cvta.to.shared.u64 t, %1; cvt.u32.u64 %0, t; }" : "=r"(a) : "l"(p));
    return a;
}

__device__ __forceinline__ float fexp(float v) {
    float x = v * 1.4426950408889634f;
    x = fmaxf(x, -126.0f);
    float kf = x + 12582912.0f;
    int   ki = __float_as_int(kf) - 0x4B400000;
    float r  = x - (kf - 12582912.0f);
    float p  = 1.3333558146e-3f;
    p = fmaf(p, r, 9.6181291076e-3f);
    p = fmaf(p, r, 5.5504108664e-2f);
    p = fmaf(p, r, 2.4022650696e-1f);
    p = fmaf(p, r, 6.9314718056e-1f);
    p = fmaf(p, r, 1.0f);
    return __int_as_float(__float_as_int(p) + (ki << 23));
}

__device__ __forceinline__ void mma_bf16(float* c, const uint32_t* a, uint32_t b0, uint32_t b1) {
    asm volatile(
        "mma.sync.aligned.m16n8k16.row.col.f32.bf16.bf16.f32 "
        "{%0,%1,%2,%3}, {%4,%5,%6,%7}, {%8,%9}, {%0,%1,%2,%3};"
        : "+f"(c[0]), "+f"(c[1]), "+f"(c[2]), "+f"(c[3])
        : "r"(a[0]), "r"(a[1]), "r"(a[2]), "r"(a[3]), "r"(b0), "r"(b1));
}
__device__ __forceinline__ void mma_f16(float* c, const uint32_t* a, uint32_t b0, uint32_t b1) {
    asm volatile(
        "mma.sync.aligned.m16n8k16.row.col.f32.f16.f16.f32 "
        "{%0,%1,%2,%3}, {%4,%5,%6,%7}, {%8,%9}, {%0,%1,%2,%3};"
        : "+f"(c[0]), "+f"(c[1]), "+f"(c[2]), "+f"(c[3])
        : "r"(a[0]), "r"(a[1]), "r"(a[2]), "r"(a[3]), "r"(b0), "r"(b1));
}
__device__ __forceinline__ void ldsm_x4(uint32_t& r0, uint32_t& r1, uint32_t& r2, uint32_t& r3,
                                        uint32_t addr) {
    asm volatile("ldmatrix.sync.aligned.m8n8.x4.shared.b16 {%0,%1,%2,%3}, [%4];"
                 : "=r"(r0), "=r"(r1), "=r"(r2), "=r"(r3) : "r"(addr));
}

// ---------------- fused preprocessing: bits | xsplit | wsplit (+enc init) ----------------
__global__ __launch_bounds__(256) void k_pre(const int* __restrict__ adj,
                                             const float* __restrict__ x,
                                             const float* __restrict__ W) {
    __shared__ __align__(16) float s[64][65];
    const int bid = blockIdx.x, tid = threadIdx.x;

    if (bid == 0 && tid < 2 * NHEADS) g_enc[tid] = 0u;

    if (bid < 4096) {
        int wid = tid >> 5, lane = tid & 31;
        const int* arow = adj + (size_t)bid * N_NODES;
        #pragma unroll
        for (int w = 0; w < 16; w++) {
            int word = wid * 16 + w;
            uint32_t m = __ballot_sync(0xFFFFFFFFu, arow[word * 32 + lane] > 0);
            if (lane == 0) g_bits[bid * 128 + word] = m;
        }
    } else if (bid < 6144) {
        int i = ((bid - 4096) * 256 + tid) * 4;
        float4 v = *(const float4*)(x + i);
        uint32_t h0 = pack_bf16x2(v.x, v.y);
        uint32_t h1 = pack_bf16x2(v.z, v.w);
        uint32_t l0 = pack_bf16x2(v.x - bf_lo_f(h0), v.y - bf_hi_f(h0));
        uint32_t l1 = pack_bf16x2(v.z - bf_lo_f(h1), v.w - bf_hi_f(h1));
        *(uint2*)(g_xhi + i) = make_uint2(h0, h1);
        *(uint2*)(g_xlo + i) = make_uint2(l0, l1);
    } else {
        int b = bid - 6144;
        int k0 = (b & 7) * 64, h = b >> 3;
        const float* Wh = W + (size_t)h * F_IN * DHEAD;
        #pragma unroll
        for (int k = 0; k < 4; k++) {
            int e = tid + k * 256; int r = e >> 4, c4 = (e & 15) * 4;
            float4 v = *(const float4*)&Wh[(size_t)(k0 + r) * DHEAD + c4];
            s[r][c4 + 0] = v.x; s[r][c4 + 1] = v.y; s[r][c4 + 2] = v.z; s[r][c4 + 3] = v.w;
        }
        __syncthreads();
        int d = tid >> 2, kb = (tid & 3) * 16;
        uint32_t hw[8], lw[8];
        #pragma unroll
        for (int e = 0; e < 8; e++) {
            float f0 = s[kb + e * 2][d], f1 = s[kb + e * 2 + 1][d];
            uint32_t hp = pack_bf16x2(f0, f1);
            hw[e] = hp;
            lw[e] = pack_bf16x2(f0 - bf_lo_f(hp), f1 - bf_hi_f(hp));
        }
        size_t base = ((size_t)h * DHEAD + d) * F_IN + k0 + kb;
        *(uint4*)(g_WT_hi + base)     = make_uint4(hw[0], hw[1], hw[2], hw[3]);
        *(uint4*)(g_WT_hi + base + 8) = make_uint4(hw[4], hw[5], hw[6], hw[7]);
        *(uint4*)(g_WT_lo + base)     = make_uint4(lw[0], lw[1], lw[2], lw[3]);
        *(uint4*)(g_WT_lo + base + 8) = make_uint4(lw[4], lw[5], lw[6], lw[7]);
    }
}

// ---------------- kernel 1: Wx = x @ W per head, split-K HMMA; fused transpose+s epilogue ----------------
__global__ __launch_bounds__(256, 2) void k_wx_mma(const float* __restrict__ a) {
    __shared__ __align__(16) char swraw[36864 + 256];
    __nv_bfloat16* s_wh = (__nv_bfloat16*)swraw;
    __nv_bfloat16* s_wl = (__nv_bfloat16*)(swraw + 18432);
    float* s_t = (float*)swraw;

    const int tid = threadIdx.x, wid = tid >> 5, lane = tid & 31;
    const int g = lane >> 2, t2 = (lane & 3) * 2;
    const int wg = wid & 3, half = wid >> 2;
    const int h = blockIdx.y, i0 = blockIdx.x * 64;
    const int r0 = i0 + wg * 16 + g, r1 = r0 + 8;

    const __nv_bfloat16* wth = g_WT_hi + (size_t)h * DHEAD * F_IN;
    const __nv_bfloat16* wtl = g_WT_lo + (size_t)h * DHEAD * F_IN;

    float acc[8][4] = {};
    for (int chunk = 0; chunk < 4; chunk++) {
        const int kc = chunk * 64;
        __syncthreads();
        #pragma unroll
        for (int it = 0; it < 4; it++) {
            int e = tid + it * 256; int r = e >> 3, c = (e & 7) * 8;
            int d = r & 63, ks = (r >> 6) * 256 + kc + c;
            *(uint4*)&s_wh[r * BPAD + c] = *(const uint4*)&wth[(size_t)d * F_IN + ks];
            *(uint4*)&s_wl[r * BPAD + c] = *(const uint4*)&wtl[(size_t)d * F_IN + ks];
        }
        __syncthreads();

        uint32_t ahi[4][4], alo[4][4];
        #pragma unroll
        for (int kf = 0; kf < 4; kf++) {
            int k = half * 256 + kc + kf * 16 + t2;
            ahi[kf][0] = *(const uint32_t*)&g_xhi[(size_t)r0 * F_IN + k];
            ahi[kf][1] = *(const uint32_t*)&g_xhi[(size_t)r1 * F_IN + k];
            ahi[kf][2] = *(const uint32_t*)&g_xhi[(size_t)r0 * F_IN + k + 8];
            ahi[kf][3] = *(const uint32_t*)&g_xhi[(size_t)r1 * F_IN + k + 8];
            alo[kf][0] = *(const uint32_t*)&g_xlo[(size_t)r0 * F_IN + k];
            alo[kf][1] = *(const uint32_t*)&g_xlo[(size_t)r1 * F_IN + k];
            alo[kf][2] = *(const uint32_t*)&g_xlo[(size_t)r0 * F_IN + k + 8];
            alo[kf][3] = *(const uint32_t*)&g_xlo[(size_t)r1 * F_IN + k + 8];
        }
        #pragma unroll
        for (int nf = 0; nf < 8; nf++) {
            const int brow = (half * 64 + nf * 8 + g) * BPAD;
            #pragma unroll
            for (int kf = 0; kf < 4; kf++) {
                const int boff = brow + kf * 16 + t2;
                uint32_t bh0 = *(const uint32_t*)&s_wh[boff];
                uint32_t bh1 = *(const uint32_t*)&s_wh[boff + 8];
                uint32_t bl0 = *(const uint32_t*)&s_wl[boff];
                uint32_t bl1 = *(const uint32_t*)&s_wl[boff + 8];
                mma_bf16(acc[nf], ahi[kf], bh0, bh1);
                mma_bf16(acc[nf], alo[kf], bh0, bh1);
                mma_bf16(acc[nf], ahi[kf], bl0, bl1);
            }
        }
    }

    __syncthreads();
    if (half == 1) {
        #pragma unroll
        for (int nf = 0; nf < 8; nf++) {
            int c = nf * 8 + t2;
            s_t[(wg * 16 + g) * 65 + c]     = acc[nf][0];
            s_t[(wg * 16 + g) * 65 + c + 1] = acc[nf][1];
            s_t[(wg * 16 + g + 8) * 65 + c]     = acc[nf][2];
            s_t[(wg * 16 + g + 8) * 65 + c + 1] = acc[nf][3];
        }
    }
    __syncthreads();
    if (half == 0) {
        #pragma unroll
        for (int nf = 0; nf < 8; nf++) {
            int c = nf * 8 + t2;
            s_t[(wg * 16 + g) * 65 + c]     += acc[nf][0];
            s_t[(wg * 16 + g) * 65 + c + 1] += acc[nf][1];
            s_t[(wg * 16 + g + 8) * 65 + c]     += acc[nf][2];
            s_t[(wg * 16 + g + 8) * 65 + c + 1] += acc[nf][3];
        }
    }
    __syncthreads();

    {
        int d = tid >> 2, nb = (tid & 3) * 16;
        uint32_t hw[8];
        #pragma unroll
        for (int e = 0; e < 8; e++) {
            float f0 = s_t[(nb + e * 2) * 65 + d];
            float f1 = s_t[(nb + e * 2 + 1) * 65 + d];
            hw[e] = pack_f16x2(f0, f1);
        }
        size_t base = ((size_t)h * DHEAD + d) * N_NODES + i0 + nb;
        *(uint4*)(g_WxT + base)     = make_uint4(hw[0], hw[1], hw[2], hw[3]);
        *(uint4*)(g_WxT + base + 8) = make_uint4(hw[4], hw[5], hw[6], hw[7]);
    }
    {
        int row = tid >> 2, tg = tid & 3;
        const float* a1 = a + h * 2 * DHEAD;
        const float* a2 = a1 + DHEAD;
        float ps = 0.0f, pd = 0.0f;
        #pragma unroll
        for (int d = tg * 16; d < tg * 16 + 16; d++) {
            float w = s_t[row * 65 + d];
            ps = fmaf(w, a1[d], ps);
            pd = fmaf(w, a2[d], pd);
        }
        ps += __shfl_xor_sync(0xFFFFFFFFu, ps, 1);
        ps += __shfl_xor_sync(0xFFFFFFFFu, ps, 2);
        pd += __shfl_xor_sync(0xFFFFFFFFu, pd, 1);
        pd += __shfl_xor_sync(0xFFFFFFFFu, pd, 2);
        if (tg == 0) {
            g_ssrc[h * N_NODES + i0 + row] = ps;
            g_sdst[h * N_NODES + i0 + row] = pd;
            atomicMax(&g_enc[h],          fenc(ps));
            atomicMax(&g_enc[NHEADS + h], fenc(pd));
        }
    }
}

// ---------------- kernel 2c: packed fp16 E/P tables (per-row scaled, all factors <= 1) ----------------
__global__ __launch_bounds__(1024) void k_prep() {
    int h = blockIdx.x, tid = threadIdx.x;
    const float maxsrc = fdec(g_enc[h]);
    const float maxdst = fdec(g_enc[NHEADS + h]);
    const float S  = maxsrc + maxdst;
    const float Mh = fmaxf(S, 0.2f * S);
    // P rows
    #pragma unroll
    for (int k = 0; k < 4; k++) {
        int i = tid + k * 1024;
        float si = g_ssrc[h * N_NODES + i];
        float P1 = fexp(si - maxsrc);
        float P2 = fexp(fmaf(0.2f, si + maxdst, -Mh));
        float sc = 1.0f / fmaxf(P1, P2);
        float p1 = P1 * sc, p2 = P2 * sc;
        g_Ppk[h * N_NODES + i] = make_uint2(pack_f16x2(p1, p1), pack_f16x2(p2, p2));
    }
    // E pairs
    #pragma unroll
    for (int k = 0; k < 2; k++) {
        int jp = tid + k * 1024;
        float sj0 = g_sdst[h * N_NODES + jp * 2];
        float sj1 = g_sdst[h * N_NODES + jp * 2 + 1];
        float e10 = fexp(sj0 - maxdst),          e11 = fexp(sj1 - maxdst);
        float e20 = fexp(0.2f * (sj0 - maxdst)), e21 = fexp(0.2f * (sj1 - maxdst));
        g_Epk[h * (N_NODES / 2) + jp] = make_uint2(pack_f16x2(e10, e11), pack_f16x2(e20, e21));
    }
}

// ---------------- kernel 3: fp16-SIMD pgen, den-via-ones-MMA, staggered overlap ----------------
#define SME_E   18432
#define SME_TOT (18432 + 16384)
#define ONES2   0x3C003C00u

__global__ __launch_bounds__(256, 2) void k_attn(const float* __restrict__ bias,
                                                 float* __restrict__ out) {
    extern __shared__ __align__(16) char sraw[];
    uint2* sE    = (uint2*)(sraw + SME_E);
    float* s_acc = (float*)sraw;
    float* s_dn  = (float*)(sraw + 16384);

    const int tid = threadIdx.x, wid = tid >> 5, lane = tid & 31;
    const int g = lane >> 2, t2 = (lane & 3) * 2;
    const int wg = wid & 3, half = wid >> 2;
    const int h = blockIdx.y, i0 = blockIdx.x * 64;

    const int r0 = i0 + wg * 16 + g, r1 = r0 + 8;
    const uint2 Pp0 = g_Ppk[h * N_NODES + r0];   // {P1P1, P2P2} row0
    const uint2 Pp1 = g_Ppk[h * N_NODES + r1];
    const int jb0 = half * 32 + t2;

    const __half* bp = g_WxT + (size_t)h * DHEAD * N_NODES;

    const int e0 = tid * 2, e1 = tid * 2 + 1;
    const int pr0 = e0 >> 3, pc0 = (e0 & 7) * 8;
    const int pr1 = e1 >> 3, pc1 = (e1 & 7) * 8;

    const uint32_t sb32 = smem_u32(sraw);
    const int mi = lane >> 3, ri = lane & 7;
    const uint32_t ldsm_lane =
        sb32 + (uint32_t)((((mi >> 1) * 8 + ri) * BPAD) * 2 + (mi & 1) * 16 + half * 64);

    // stage packed E table (16KB = 1024 uint4)
    {
        const uint4* src = (const uint4*)(g_Epk + h * (N_NODES / 2));
        uint4* dst = (uint4*)sE;
        #pragma unroll
        for (int k = 0; k < 4; k++) dst[tid + k * 256] = src[tid + k * 256];
    }
    {
        __half* bh = (__half*)sraw;
        *(uint4*)&bh[pr0 * BPAD + pc0] = *(const uint4*)(bp + (size_t)pr0 * N_NODES + pc0);
        *(uint4*)&bh[pr1 * BPAD + pc1] = *(const uint4*)(bp + (size_t)pr1 * N_NODES + pc1);
    }
    uint32_t mn0 = g_bits[r0 * 128 + half];
    uint32_t mn1 = g_bits[r1 * 128 + half];
    __syncthreads();

    uint32_t aF[2][2][4];

    // fp16-SIMD pgen: p-pair = mul/max/mul(mask); mask word via IMAD bit expansion
    #define PGEN(jt, buf)                                                          \
    do {                                                                           \
        const int _j = (jt) * 64;                                                  \
        uint2 eA0 = sE[(_j + jb0) >> 1];                                           \
        uint2 eB0 = sE[(_j + jb0 + 8) >> 1];                                       \
        uint2 eA1 = sE[(_j + jb0 + 16) >> 1];                                      \
        uint2 eB1 = sE[(_j + jb0 + 24) >> 1];                                      \
        _Pragma("unroll")                                                          \
        for (int kf = 0; kf < 2; kf++) {                                           \
            const uint2 eA = kf ? eA1 : eA0;                                       \
            const uint2 eB = kf ? eB1 : eB0;                                       \
            const uint32_t ma0 = mn0 >> (kf * 16 + t2);                            \
            const uint32_t ma1 = mn1 >> (kf * 16 + t2);                            \
            uint32_t mA0 = (ma0 & 1u) * 0x3C00u + (ma0 & 2u) * 0x1E000000u;        \
            uint32_t mB0 = (ma0 & 0x100u) * 0x3Cu + (ma0 & 0x200u) * 0x1E0000u;    \
            uint32_t mA1 = (ma1 & 1u) * 0x3C00u + (ma1 & 2u) * 0x1E000000u;        \
            uint32_t mB1 = (ma1 & 0x100u) * 0x3Cu + (ma1 & 0x200u) * 0x1E0000u;    \
            uint32_t vA0 = hmax2(hmul2(Pp0.x, eA.x), hmul2(Pp0.y, eA.y));          \
            uint32_t vB0 = hmax2(hmul2(Pp0.x, eB.x), hmul2(Pp0.y, eB.y));          \
            uint32_t vA1 = hmax2(hmul2(Pp1.x, eA.x), hmul2(Pp1.y, eA.y));          \
            uint32_t vB1 = hmax2(hmul2(Pp1.x, eB.x), hmul2(Pp1.y, eB.y));          \
            aF[buf][kf][0] = hmul2(vA0, mA0);                                      \
            aF[buf][kf][1] = hmul2(vA1, mA1);                                      \
            aF[buf][kf][2] = hmul2(vB0, mB0);                                      \
            aF[buf][kf][3] = hmul2(vB1, mB1);                                      \
        }                                                                          \
    } while (0)

    #define MMA_BLOCK(cur)                                                         \
    do {                                                                           \
        const uint32_t bbase = ldsm_lane + (cur) * 9216u;                          \
        _Pragma("unroll")                                                          \
        for (int nfp = 0; nfp < 4; nfp++) {                                        \
            _Pragma("unroll")                                                      \
            for (int kf = 0; kf < 2; kf++) {                                       \
                uint32_t b0, b1, b2, b3;                                           \
                ldsm_x4(b0, b1, b2, b3, bbase + nfp * 2304u + kf * 32u);           \
                mma_f16(acc[2 * nfp],     aF[cur][kf], b0, b1);                    \
                mma_f16(acc[2 * nfp + 1], aF[cur][kf], b2, b3);                    \
            }                                                                      \
        }                                                                          \
        mma_f16(dacc, aF[cur][0], ONES2, ONES2);                                   \
        mma_f16(dacc, aF[cur][1], ONES2, ONES2);                                   \
    } while (0)

    PGEN(0, 0);

    mn0 = g_bits[r0 * 128 + 2 + half];
    mn1 = g_bits[r1 * 128 + 2 + half];
    uint4 nh0 = *(const uint4*)(bp + (size_t)pr0 * N_NODES + 64 + pc0);
    uint4 nh1 = *(const uint4*)(bp + (size_t)pr1 * N_NODES + 64 + pc1);

    float acc[8][4] = {};
    float dacc[4] = {};

    for (int t = 0; t < 64; t++) {
        const int cur = t & 1;

        if (half == 0) {
            MMA_BLOCK(cur);
            if (t < 63) PGEN(t + 1, 1 - cur);
        } else {
            if (t < 63) PGEN(t + 1, 1 - cur);
            MMA_BLOCK(cur);
        }

        if (t < 63) {
            __half* bh = (__half*)(sraw + (1 - cur) * 9216);
            *(uint4*)&bh[pr0 * BPAD + pc0] = nh0;
            *(uint4*)&bh[pr1 * BPAD + pc1] = nh1;
            if (t < 62) {
                const int jn2 = (t + 2) * 64;
                mn0 = g_bits[r0 * 128 + (t + 2) * 2 + half];
                mn1 = g_bits[r1 * 128 + (t + 2) * 2 + half];
                nh0 = *(const uint4*)(bp + (size_t)pr0 * N_NODES + jn2 + pc0);
                nh1 = *(const uint4*)(bp + (size_t)pr1 * N_NODES + jn2 + pc1);
            }
        }
        __syncthreads();
    }
    #undef PGEN
    #undef MMA_BLOCK

    // den from ones-MMA: all lanes in a quad hold full half-row sums
    const float den0 = dacc[0];
    const float den1 = dacc[2];

    if (half == 1) {
        if ((lane & 3) == 0) {
            s_dn[wg * 16 + g]     = den0;
            s_dn[wg * 16 + g + 8] = den1;
        }
        #pragma unroll
        for (int nf = 0; nf < 8; nf++) {
            *(float2*)&s_acc[(wg * 16 + g) * 64 + nf * 8 + t2]     = make_float2(acc[nf][0], acc[nf][1]);
            *(float2*)&s_acc[(wg * 16 + g + 8) * 64 + nf * 8 + t2] = make_float2(acc[nf][2], acc[nf][3]);
        }
    }
    __syncthreads();
    if (half == 0) {
        const float inv0 = 1.0f / (den0 + s_dn[wg * 16 + g]);
        const float inv1 = 1.0f / (den1 + s_dn[wg * 16 + g + 8]);
        float* orow0 = out + (size_t)r0 * (NHEADS * DHEAD) + h * DHEAD;
        float* orow1 = out + (size_t)r1 * (NHEADS * DHEAD) + h * DHEAD;
        #pragma unroll
        for (int nf = 0; nf < 8; nf++) {
            float2 x0 = *(const float2*)&s_acc[(wg * 16 + g) * 64 + nf * 8 + t2];
            float2 x1 = *(const float2*)&s_acc[(wg * 16 + g + 8) * 64 + nf * 8 + t2];
            float2 b2 = *(const float2*)&bias[h * DHEAD + nf * 8 + t2];
            float2 o0, o1;
            o0.x = fmaxf(fmaf(acc[nf][0] + x0.x, inv0, b2.x), 0.0f);
            o0.y = fmaxf(fmaf(acc[nf][1] + x0.y, inv0, b2.y), 0.0f);
            o1.x = fmaxf(fmaf(acc[nf][2] + x1.x, inv1, b2.x), 0.0f);
            o1.y = fmaxf(fmaf(acc[nf][3] + x1.y, inv1, b2.y), 0.0f);
            *(float2*)(orow0 + nf * 8 + t2) = o0;
            *(float2*)(orow1 + nf * 8 + t2) = o1;
        }
    }
}

// ---------------- launch ----------------
extern "C" void kernel_launch(void* const* d_in, const int* in_sizes, int n_in,
                              void* d_out, int out_size) {
    const float* x    = (const float*)d_in[0];
    const int*   adj  = (const int*)  d_in[1];
    const float* W    = (const float*)d_in[2];
    const float* a    = (const float*)d_in[3];
    const float* bias = (const float*)d_in[4];
    float* out = (float*)d_out;

    cudaFuncSetAttribute(k_attn, cudaFuncAttributeMaxDynamicSharedMemorySize, SME_TOT);

    k_pre   <<<6176, 256>>>(adj, x, W);
    k_wx_mma<<<dim3(N_NODES / 64, NHEADS), 256>>>(a);
    k_prep  <<<NHEADS, 1024>>>();
    k_attn  <<<dim3(N_NODES / 64, NHEADS), 256, SME_TOT>>>(bias, out);
}

// round 15
// speedup vs baseline: 1.1533x; 1.1533x over previous
#include <cuda_runtime.h>
#include <cuda_fp16.h>
#include <stdint.h>

#define N_NODES 4096
#define F_IN    512
#define NHEADS  4
#define DHEAD   64
#define BPAD    72

// ---------------- device scratch ----------------
__device__ float    g_ssrc[NHEADS * N_NODES];
__device__ float    g_sdst[NHEADS * N_NODES];
__device__ unsigned g_enc[2 * NHEADS];
__device__ __half   g_WxT[NHEADS * DHEAD * N_NODES];   // fp16 [h][d][n]
__device__ __half   g_xf[N_NODES * F_IN];              // x fp16
__device__ __half   g_WTf[NHEADS * DHEAD * F_IN];      // W^T fp16 [h][d][k]
__device__ float2   g_E[NHEADS * N_NODES];             // {Ej1, Ej2}
__device__ float4   g_P[NHEADS * N_NODES];             // {Pi1', Pi2', -, -} per-row scaled
__device__ uint32_t g_bits[N_NODES * 128];             // adj bitmask, 2MB

// ---------------- helpers ----------------
__device__ __forceinline__ uint32_t pack_f16x2(float lo, float hi) {
    uint32_t r;
    asm("cvt.rn.f16x2.f32 %0, %1, %2;" : "=r"(r) : "f"(hi), "f"(lo));
    return r;
}

__device__ __forceinline__ unsigned fenc(float f) {
    unsigned u = __float_as_uint(f);
    return (u & 0x80000000u) ? ~u : (u | 0x80000000u);
}
__device__ __forceinline__ float fdec(unsigned u) {
    unsigned b = (u & 0x80000000u) ? (u & 0x7FFFFFFFu) : ~u;
    return __uint_as_float(b);
}

__device__ __forceinline__ uint32_t smem_u32(const void* p) {
    uint32_t a;
    asm("{ .reg .u64 t; cvta.to.shared.u64 t, %1; cvt.u32.u64 %0, t; }" : "=r"(a) : "l"(p));
    return a;
}

__device__ __forceinline__ float fexp(float v) {
    float x = v * 1.4426950408889634f;
    x = fmaxf(x, -126.0f);
    float kf = x + 12582912.0f;
    int   ki = __float_as_int(kf) - 0x4B400000;
    float r  = x - (kf - 12582912.0f);
    float p  = 1.3333558146e-3f;
    p = fmaf(p, r, 9.6181291076e-3f);
    p = fmaf(p, r, 5.5504108664e-2f);
    p = fmaf(p, r, 2.4022650696e-1f);
    p = fmaf(p, r, 6.9314718056e-1f);
    p = fmaf(p, r, 1.0f);
    return __int_as_float(__float_as_int(p) + (ki << 23));
}

__device__ __forceinline__ void mma_f16(float* c, const uint32_t* a, uint32_t b0, uint32_t b1) {
    asm volatile(
        "mma.sync.aligned.m16n8k16.row.col.f32.f16.f16.f32 "
        "{%0,%1,%2,%3}, {%4,%5,%6,%7}, {%8,%9}, {%0,%1,%2,%3};"
        : "+f"(c[0]), "+f"(c[1]), "+f"(c[2]), "+f"(c[3])
        : "r"(a[0]), "r"(a[1]), "r"(a[2]), "r"(a[3]), "r"(b0), "r"(b1));
}
__device__ __forceinline__ void ldsm_x4(uint32_t& r0, uint32_t& r1, uint32_t& r2, uint32_t& r3,
                                        uint32_t addr) {
    asm volatile("ldmatrix.sync.aligned.m8n8.x4.shared.b16 {%0,%1,%2,%3}, [%4];"
                 : "=r"(r0), "=r"(r1), "=r"(r2), "=r"(r3) : "r"(addr));
}

// ---------------- fused preprocessing: bits | x->fp16 | W->fp16^T (+enc init) ----------------
// grid = 4096 (bits) + 1024 (x) + 32 (W) = 5152 blocks x 256 threads
__global__ __launch_bounds__(256) void k_pre(const int* __restrict__ adj,
                                             const float* __restrict__ x,
                                             const float* __restrict__ W) {
    __shared__ __align__(16) float s[64][65];
    const int bid = blockIdx.x, tid = threadIdx.x;

    if (bid == 0 && tid < 2 * NHEADS) g_enc[tid] = 0u;

    if (bid < 4096) {
        int wid = tid >> 5, lane = tid & 31;
        const int* arow = adj + (size_t)bid * N_NODES;
        #pragma unroll
        for (int w = 0; w < 16; w++) {
            int word = wid * 16 + w;
            uint32_t m = __ballot_sync(0xFFFFFFFFu, arow[word * 32 + lane] > 0);
            if (lane == 0) g_bits[bid * 128 + word] = m;
        }
    } else if (bid < 5120) {
        int i = ((bid - 4096) * 256 + tid) * 8;
        float4 v0 = *(const float4*)(x + i);
        float4 v1 = *(const float4*)(x + i + 4);
        uint4 o;
        o.x = pack_f16x2(v0.x, v0.y);
        o.y = pack_f16x2(v0.z, v0.w);
        o.z = pack_f16x2(v1.x, v1.y);
        o.w = pack_f16x2(v1.z, v1.w);
        *(uint4*)(g_xf + i) = o;
    } else {
        int b = bid - 5120;
        int k0 = (b & 7) * 64, h = b >> 3;
        const float* Wh = W + (size_t)h * F_IN * DHEAD;
        #pragma unroll
        for (int k = 0; k < 4; k++) {
            int e = tid + k * 256; int r = e >> 4, c4 = (e & 15) * 4;
            float4 v = *(const float4*)&Wh[(size_t)(k0 + r) * DHEAD + c4];
            s[r][c4 + 0] = v.x; s[r][c4 + 1] = v.y; s[r][c4 + 2] = v.z; s[r][c4 + 3] = v.w;
        }
        __syncthreads();
        int d = tid >> 2, kb = (tid & 3) * 16;
        uint32_t hw[8];
        #pragma unroll
        for (int e = 0; e < 8; e++) {
            float f0 = s[kb + e * 2][d], f1 = s[kb + e * 2 + 1][d];
            hw[e] = pack_f16x2(f0, f1);
        }
        size_t base = ((size_t)h * DHEAD + d) * F_IN + k0 + kb;
        *(uint4*)(g_WTf + base)     = make_uint4(hw[0], hw[1], hw[2], hw[3]);
        *(uint4*)(g_WTf + base + 8) = make_uint4(hw[4], hw[5], hw[6], hw[7]);
    }
}

// ---------------- kernel 1: Wx = x @ W per head, fp16 single-term split-K HMMA ----------------
__global__ __launch_bounds__(256, 2) void k_wx_mma(const float* __restrict__ a) {
    __shared__ __align__(16) char swraw[18688];
    __half* s_w = (__half*)swraw;                  // 128 rows x BPAD fp16 (18.4KB)
    float* s_t = (float*)swraw;                    // 64 x 65 fp32 (16.6KB) epilogue reuse

    const int tid = threadIdx.x, wid = tid >> 5, lane = tid & 31;
    const int g = lane >> 2, t2 = (lane & 3) * 2;
    const int wg = wid & 3, half = wid >> 2;
    const int h = blockIdx.y, i0 = blockIdx.x * 64;
    const int r0 = i0 + wg * 16 + g, r1 = r0 + 8;

    const __half* wt = g_WTf + (size_t)h * DHEAD * F_IN;

    float acc[8][4] = {};
    for (int chunk = 0; chunk < 4; chunk++) {
        const int kc = chunk * 64;
        __syncthreads();
        #pragma unroll
        for (int it = 0; it < 4; it++) {
            int e = tid + it * 256; int r = e >> 3, c = (e & 7) * 8;
            int d = r & 63, ks = (r >> 6) * 256 + kc + c;
            *(uint4*)&s_w[r * BPAD + c] = *(const uint4*)&wt[(size_t)d * F_IN + ks];
        }
        __syncthreads();

        uint32_t af[4][4];
        #pragma unroll
        for (int kf = 0; kf < 4; kf++) {
            int k = half * 256 + kc + kf * 16 + t2;
            af[kf][0] = *(const uint32_t*)&g_xf[(size_t)r0 * F_IN + k];
            af[kf][1] = *(const uint32_t*)&g_xf[(size_t)r1 * F_IN + k];
            af[kf][2] = *(const uint32_t*)&g_xf[(size_t)r0 * F_IN + k + 8];
            af[kf][3] = *(const uint32_t*)&g_xf[(size_t)r1 * F_IN + k + 8];
        }
        #pragma unroll
        for (int nf = 0; nf < 8; nf++) {
            const int brow = (half * 64 + nf * 8 + g) * BPAD;
            #pragma unroll
            for (int kf = 0; kf < 4; kf++) {
                const int boff = brow + kf * 16 + t2;
                uint32_t b0 = *(const uint32_t*)&s_w[boff];
                uint32_t b1 = *(const uint32_t*)&s_w[boff + 8];
                mma_f16(acc[nf], af[kf], b0, b1);
            }
        }
    }

    // ---- merge split-K halves into s_t (pad-65 rows) ----
    __syncthreads();
    if (half == 1) {
        #pragma unroll
        for (int nf = 0; nf < 8; nf++) {
            int c = nf * 8 + t2;
            s_t[(wg * 16 + g) * 65 + c]     = acc[nf][0];
            s_t[(wg * 16 + g) * 65 + c + 1] = acc[nf][1];
            s_t[(wg * 16 + g + 8) * 65 + c]     = acc[nf][2];
            s_t[(wg * 16 + g + 8) * 65 + c + 1] = acc[nf][3];
        }
    }
    __syncthreads();
    if (half == 0) {
        #pragma unroll
        for (int nf = 0; nf < 8; nf++) {
            int c = nf * 8 + t2;
            s_t[(wg * 16 + g) * 65 + c]     += acc[nf][0];
            s_t[(wg * 16 + g) * 65 + c + 1] += acc[nf][1];
            s_t[(wg * 16 + g + 8) * 65 + c]     += acc[nf][2];
            s_t[(wg * 16 + g + 8) * 65 + c + 1] += acc[nf][3];
        }
    }
    __syncthreads();

    // ---- fp16 transposed write ----
    {
        int d = tid >> 2, nb = (tid & 3) * 16;
        uint32_t hw[8];
        #pragma unroll
        for (int e = 0; e < 8; e++) {
            float f0 = s_t[(nb + e * 2) * 65 + d];
            float f1 = s_t[(nb + e * 2 + 1) * 65 + d];
            hw[e] = pack_f16x2(f0, f1);
        }
        size_t base = ((size_t)h * DHEAD + d) * N_NODES + i0 + nb;
        *(uint4*)(g_WxT + base)     = make_uint4(hw[0], hw[1], hw[2], hw[3]);
        *(uint4*)(g_WxT + base + 8) = make_uint4(hw[4], hw[5], hw[6], hw[7]);
    }
    // ---- s_src/s_dst + per-head maxima ----
    {
        int row = tid >> 2, tg = tid & 3;
        const float* a1 = a + h * 2 * DHEAD;
        const float* a2 = a1 + DHEAD;
        float ps = 0.0f, pd = 0.0f;
        #pragma unroll
        for (int d = tg * 16; d < tg * 16 + 16; d++) {
            float w = s_t[row * 65 + d];
            ps = fmaf(w, a1[d], ps);
            pd = fmaf(w, a2[d], pd);
        }
        ps += __shfl_xor_sync(0xFFFFFFFFu, ps, 1);
        ps += __shfl_xor_sync(0xFFFFFFFFu, ps, 2);
        pd += __shfl_xor_sync(0xFFFFFFFFu, pd, 1);
        pd += __shfl_xor_sync(0xFFFFFFFFu, pd, 2);
        if (tg == 0) {
            g_ssrc[h * N_NODES + i0 + row] = ps;
            g_sdst[h * N_NODES + i0 + row] = pd;
            atomicMax(&g_enc[h],          fenc(ps));
            atomicMax(&g_enc[NHEADS + h], fenc(pd));
        }
    }
}

// ---------------- kernel 2c: E/P tables per head (per-row scaled) ----------------
__global__ __launch_bounds__(1024) void k_prep() {
    int h = blockIdx.x, tid = threadIdx.x;
    const float maxsrc = fdec(g_enc[h]);
    const float maxdst = fdec(g_enc[NHEADS + h]);
    const float S  = maxsrc + maxdst;
    const float Mh = fmaxf(S, 0.2f * S);
    const float r_ = Mh - 0.2f * S;
    const float c_ = 0.2f * maxsrc + 0.5f * r_;
    const float d_ = 0.2f * maxdst + 0.5f * r_;
    const float maxE2 = fexp(-0.5f * r_);
    #pragma unroll
    for (int k = 0; k < 4; k++) {
        int j = tid + k * 1024;
        float sj = g_sdst[h * N_NODES + j];
        g_E[h * N_NODES + j] = make_float2(fexp(sj - maxdst), fexp(fmaf(0.2f, sj, -d_)));
        float si = g_ssrc[h * N_NODES + j];
        float Pi1 = fexp(si - maxsrc);
        float Pi2 = fexp(fmaf(0.2f, si, -c_));
        float sc = 1.0f / fmaxf(Pi1, Pi2 * maxE2);
        g_P[h * N_NODES + j] = make_float4(Pi1 * sc, Pi2 * sc, 0.0f, 0.0f);
    }
}

// ---------------- kernel 3 (R13, best known): staggered MMA/pgen, ldmatrix B, max-trick p ----------------
#define SME_E   18432
#define SME_TOT (18432 + 32768)

__global__ __launch_bounds__(256, 2) void k_attn(const float* __restrict__ bias,
                                                 float* __restrict__ out) {
    extern __shared__ __align__(16) char sraw[];
    float* sE    = (float*)(sraw + SME_E);
    float* s_acc = (float*)sraw;
    float* s_dn  = (float*)(sraw + 16384);

    const int tid = threadIdx.x, wid = tid >> 5, lane = tid & 31;
    const int g = lane >> 2, t2 = (lane & 3) * 2;
    const int wg = wid & 3, half = wid >> 2;
    const int h = blockIdx.y, i0 = blockIdx.x * 64;

    const int r0 = i0 + wg * 16 + g, r1 = r0 + 8;
    const float4 P0 = g_P[h * N_NODES + r0];
    const float4 P1 = g_P[h * N_NODES + r1];
    const int jb0 = half * 32 + t2;

    const __half* bp = g_WxT + (size_t)h * DHEAD * N_NODES;

    const int e0 = tid * 2, e1 = tid * 2 + 1;
    const int pr0 = e0 >> 3, pc0 = (e0 & 7) * 8;
    const int pr1 = e1 >> 3, pc1 = (e1 & 7) * 8;

    const uint32_t sb32 = smem_u32(sraw);
    const int mi = lane >> 3, ri = lane & 7;
    const uint32_t ldsm_lane =
        sb32 + (uint32_t)((((mi >> 1) * 8 + ri) * BPAD) * 2 + (mi & 1) * 16 + half * 64);

    {
        const float4* src = (const float4*)(g_E + h * N_NODES);
        float4* dst = (float4*)sE;
        #pragma unroll
        for (int k = 0; k < 8; k++) dst[tid + k * 256] = src[tid + k * 256];
    }
    {
        __half* bh = (__half*)sraw;
        *(uint4*)&bh[pr0 * BPAD + pc0] = *(const uint4*)(bp + (size_t)pr0 * N_NODES + pc0);
        *(uint4*)&bh[pr1 * BPAD + pc1] = *(const uint4*)(bp + (size_t)pr1 * N_NODES + pc1);
    }
    uint32_t mn0 = g_bits[r0 * 128 + half];
    uint32_t mn1 = g_bits[r1 * 128 + half];
    __syncthreads();

    uint32_t aF[2][2][4];
    float den0 = 0.0f, den1 = 0.0f;

    #define PGEN(jt, buf)                                                          \
    do {                                                                           \
        const int _j = (jt) * 64;                                                  \
        float4 EA0 = *(const float4*)&sE[(_j + jb0) * 2];                          \
        float4 EB0 = *(const float4*)&sE[(_j + jb0 + 8) * 2];                      \
        float4 EA1 = *(const float4*)&sE[(_j + jb0 + 16) * 2];                     \
        float4 EB1 = *(const float4*)&sE[(_j + jb0 + 24) * 2];                     \
        _Pragma("unroll")                                                          \
        for (int kf = 0; kf < 2; kf++) {                                           \
            const float4 eA = kf ? EA1 : EA0;                                      \
            const float4 eB = kf ? EB1 : EB0;                                      \
            const uint32_t ma0 = mn0 >> (kf * 16 + t2);                            \
            const uint32_t ma1 = mn1 >> (kf * 16 + t2);                            \
            float p00 = (ma0 & 1u)   ? fmaxf(P0.x * eA.x, P0.y * eA.y) : 0.0f;     \
            float p01 = (ma0 & 2u)   ? fmaxf(P0.x * eA.z, P0.y * eA.w) : 0.0f;     \
            float p08 = (ma0 & 256u) ? fmaxf(P0.x * eB.x, P0.y * eB.y) : 0.0f;     \
            float p09 = (ma0 & 512u) ? fmaxf(P0.x * eB.z, P0.y * eB.w) : 0.0f;     \
            float p10 = (ma1 & 1u)   ? fmaxf(P1.x * eA.x, P1.y * eA.y) : 0.0f;     \
            float p11 = (ma1 & 2u)   ? fmaxf(P1.x * eA.z, P1.y * eA.w) : 0.0f;     \
            float p18 = (ma1 & 256u) ? fmaxf(P1.x * eB.x, P1.y * eB.y) : 0.0f;     \
            float p19 = (ma1 & 512u) ? fmaxf(P1.x * eB.z, P1.y * eB.w) : 0.0f;     \
            den0 += (p00 + p01) + (p08 + p09);                                     \
            den1 += (p10 + p11) + (p18 + p19);                                     \
            aF[buf][kf][0] = pack_f16x2(p00, p01);                                 \
            aF[buf][kf][1] = pack_f16x2(p10, p11);                                 \
            aF[buf][kf][2] = pack_f16x2(p08, p09);                                 \
            aF[buf][kf][3] = pack_f16x2(p18, p19);                                 \
        }                                                                          \
    } while (0)

    #define MMA_BLOCK(cur)                                                         \
    do {                                                                           \
        const uint32_t bbase = ldsm_lane + (cur) * 9216u;                          \
        _Pragma("unroll")                                                          \
        for (int nfp = 0; nfp < 4; nfp++) {                                        \
            _Pragma("unroll")                                                      \
            for (int kf = 0; kf < 2; kf++) {                                       \
                uint32_t b0, b1, b2, b3;                                           \
                ldsm_x4(b0, b1, b2, b3, bbase + nfp * 2304u + kf * 32u);           \
                mma_f16(acc[2 * nfp],     aF[cur][kf], b0, b1);                    \
                mma_f16(acc[2 * nfp + 1], aF[cur][kf], b2, b3);                    \
            }                                                                      \
        }                                                                          \
    } while (0)

    PGEN(0, 0);

    mn0 = g_bits[r0 * 128 + 2 + half];
    mn1 = g_bits[r1 * 128 + 2 + half];
    uint4 nh0 = *(const uint4*)(bp + (size_t)pr0 * N_NODES + 64 + pc0);
    uint4 nh1 = *(const uint4*)(bp + (size_t)pr1 * N_NODES + 64 + pc1);

    float acc[8][4] = {};

    for (int t = 0; t < 64; t++) {
        const int cur = t & 1;

        if (half == 0) {
            MMA_BLOCK(cur);
            if (t < 63) PGEN(t + 1, 1 - cur);
        } else {
            if (t < 63) PGEN(t + 1, 1 - cur);
            MMA_BLOCK(cur);
        }

        if (t < 63) {
            __half* bh = (__half*)(sraw + (1 - cur) * 9216);
            *(uint4*)&bh[pr0 * BPAD + pc0] = nh0;
            *(uint4*)&bh[pr1 * BPAD + pc1] = nh1;
            if (t < 62) {
                const int jn2 = (t + 2) * 64;
                mn0 = g_bits[r0 * 128 + (t + 2) * 2 + half];
                mn1 = g_bits[r1 * 128 + (t + 2) * 2 + half];
                nh0 = *(const uint4*)(bp + (size_t)pr0 * N_NODES + jn2 + pc0);
                nh1 = *(const uint4*)(bp + (size_t)pr1 * N_NODES + jn2 + pc1);
            }
        }
        __syncthreads();
    }
    #undef PGEN
    #undef MMA_BLOCK

    den0 += __shfl_xor_sync(0xFFFFFFFFu, den0, 1);
    den0 += __shfl_xor_sync(0xFFFFFFFFu, den0, 2);
    den1 += __shfl_xor_sync(0xFFFFFFFFu, den1, 1);
    den1 += __shfl_xor_sync(0xFFFFFFFFu, den1, 2);

    if (half == 1) {
        if ((lane & 3) == 0) {
            s_dn[wg * 16 + g]     = den0;
            s_dn[wg * 16 + g + 8] = den1;
        }
        #pragma unroll
        for (int nf = 0; nf < 8; nf++) {
            *(float2*)&s_acc[(wg * 16 + g) * 64 + nf * 8 + t2]     = make_float2(acc[nf][0], acc[nf][1]);
            *(float2*)&s_acc[(wg * 16 + g + 8) * 64 + nf * 8 + t2] = make_float2(acc[nf][2], acc[nf][3]);
        }
    }
    __syncthreads();
    if (half == 0) {
        const float inv0 = 1.0f / (den0 + s_dn[wg * 16 + g]);
        const float inv1 = 1.0f / (den1 + s_dn[wg * 16 + g + 8]);
        float* orow0 = out + (size_t)r0 * (NHEADS * DHEAD) + h * DHEAD;
        float* orow1 = out + (size_t)r1 * (NHEADS * DHEAD) + h * DHEAD;
        #pragma unroll
        for (int nf = 0; nf < 8; nf++) {
            float2 x0 = *(const float2*)&s_acc[(wg * 16 + g) * 64 + nf * 8 + t2];
            float2 x1 = *(const float2*)&s_acc[(wg * 16 + g + 8) * 64 + nf * 8 + t2];
            float2 b2 = *(const float2*)&bias[h * DHEAD + nf * 8 + t2];
            float2 o0, o1;
            o0.x = fmaxf(fmaf(acc[nf][0] + x0.x, inv0, b2.x), 0.0f);
            o0.y = fmaxf(fmaf(acc[nf][1] + x0.y, inv0, b2.y), 0.0f);
            o1.x = fmaxf(fmaf(acc[nf][2] + x1.x, inv1, b2.x), 0.0f);
            o1.y = fmaxf(fmaf(acc[nf][3] + x1.y, inv1, b2.y), 0.0f);
            *(float2*)(orow0 + nf * 8 + t2) = o0;
            *(float2*)(orow1 + nf * 8 + t2) = o1;
        }
    }
}

// ---------------- launch ----------------
extern "C" void kernel_launch(void* const* d_in, const int* in_sizes, int n_in,
                              void* d_out, int out_size) {
    const float* x    = (const float*)d_in[0];
    const int*   adj  = (const int*)  d_in[1];
    const float* W    = (const float*)d_in[2];
    const float* a    = (const float*)d_in[3];
    const float* bias = (const float*)d_in[4];
    float* out = (float*)d_out;

    cudaFuncSetAttribute(k_attn, cudaFuncAttributeMaxDynamicSharedMemorySize, SME_TOT);

    k_pre   <<<5152, 256>>>(adj, x, W);
    k_wx_mma<<<dim3(N_NODES / 64, NHEADS), 256>>>(a);
    k_prep  <<<NHEADS, 1024>>>();
    k_attn  <<<dim3(N_NODES / 64, NHEADS), 256, SME_TOT>>>(bias, out);
}